// round 7
// baseline (speedup 1.0000x reference)
#include <cuda_runtime.h>
#include <cstdint>

#define NIMG 256
#define IMGS_PER_BLK 8

// Conv layers 0..5: cin {3,344,352,686,679,1246} cout {344,352,686,679,1246,973}
// conv H=W {32,32,16,16,8,8}, pool after 1,3,5.
// Activation words/pixel (32 ch each): l0out 12, pool->l2 12, l2out 22, l3out 22,
// pool->l4 22, l4out 40, l5out 32, pool->FC 32.
// Layer 0: bitwise XNOR kernel. Layers 1-5: mma.sync m16n8k32 s8 (values {-1,0,+1}, exact).

__device__ uint32_t g_bufA[(size_t)NIMG * 32 * 32 * 12];
__device__ uint32_t g_bufB[(size_t)NIMG * 32 * 32 * 12];
__device__ uint32_t g_wpk0[3456];    // layer0 packed bits [wi][tap][32cl]
__device__ int      g_pw0[3456];     // layer0 per-tap weight popcounts
__device__ float2   g_th[4480];      // thresholds, 64-padded, cum {0,384,768,1472,2176,3456}
__device__ uint32_t g_fcpk[10 * 16 * 32];
__device__ __align__(16) uint2 g_wi8[3515904];  // s8 B-fragment weights layers 1-5

// ---------------------------------------------------------------------------
__device__ __forceinline__ void imma_16832(int* c, const uint32_t* a, uint2 b) {
    asm volatile(
        "mma.sync.aligned.m16n8k32.row.col.s32.s8.s8.s32 "
        "{%0,%1,%2,%3}, {%4,%5,%6,%7}, {%8,%9}, {%0,%1,%2,%3};"
        : "+r"(c[0]), "+r"(c[1]), "+r"(c[2]), "+r"(c[3])
        : "r"(a[0]), "r"(a[1]), "r"(a[2]), "r"(a[3]), "r"(b.x), "r"(b.y));
}

// ---------------------------------------------------------------------------
// Pack: x activations + layer0 weight bits
__global__ void pack_xw_kernel(const float* __restrict__ x, const float* __restrict__ w0,
                               uint32_t* __restrict__ dstx, uint32_t* __restrict__ dstw)
{
    int idx = blockIdx.x * blockDim.x + threadIdx.x;
    if (idx < NIMG * 1024) {
        int n = idx >> 10, pix = idx & 1023;
        const float* xb = x + (size_t)n * 3 * 1024 + pix;
        uint32_t w = 0;
        if (xb[0]    > 0.f) w |= 1u;
        if (xb[1024] > 0.f) w |= 2u;
        if (xb[2048] > 0.f) w |= 4u;
        dstx[idx] = w;
        return;
    }
    int warp = (idx >> 5) - 8192;
    int lane = idx & 31;
    if (warp >= 3456) return;
    int cl = warp & 31; int s = warp >> 5;
    int tap = s % 9; int wi = s / 9;
    int co = wi * 32 + cl;
    float v = (co < 344 && lane < 3) ? w0[((size_t)co * 3 + lane) * 9 + tap] : 0.f;
    uint32_t bits = __ballot_sync(0xFFFFFFFFu, v > 0.f);
    if (lane == 0) dstw[warp] = bits;
}

// Pack: FC bits + layer0 popcounts + all thresholds (64-padded layout)
__global__ void pack_misc_kernel(const uint32_t* __restrict__ wpk0,
                                 const float* __restrict__ fcw,
                                 const float* __restrict__ p0, const float* __restrict__ p1,
                                 const float* __restrict__ p2, const float* __restrict__ p3,
                                 const float* __restrict__ p4, const float* __restrict__ p5,
                                 int* __restrict__ pw, float2* __restrict__ th,
                                 uint32_t* __restrict__ fcpk)
{
    int idx = blockIdx.x * blockDim.x + threadIdx.x;
    if (idx < 163840) {
        int warp = idx >> 5, lane = idx & 31;
        int wi = warp & 31; int r = warp >> 5;
        int s = r & 15; int o = r >> 4;
        int c = wi * 32 + lane;
        float v = (c < 973) ? fcw[(size_t)o * 15568 + c * 16 + s] : 0.f;
        uint32_t bits = __ballot_sync(0xFFFFFFFFu, v > 0.f);
        if (lane == 0) fcpk[warp] = bits;
    } else if (idx < 163840 + 3456) {
        int i1 = idx - 163840;
        pw[i1] = __popc(wpk0[i1]);
    } else if (idx < 163840 + 3456 + 4480) {
        int i2 = idx - 163840 - 3456;
        const int cum[7]  = {0, 384, 768, 1472, 2176, 3456, 4480};
        const int cout[6] = {344, 352, 686, 679, 1246, 973};
        int l = 0;
#pragma unroll
        for (int i = 1; i < 6; ++i) if (i2 >= cum[i]) l = i;
        const float* p = (l == 0) ? p0 : (l == 1) ? p1 : (l == 2) ? p2
                        : (l == 3) ? p3 : (l == 4) ? p4 : p5;
        int c = i2 - cum[l];
        int Co = cout[l];
        float2 t;
        if (c < Co) {
            float gg = p[c], bb = p[Co + c], mm = p[2 * Co + c], vv = p[3 * Co + c];
            float sc = gg * rsqrtf(vv + 1e-5f);
            t.x = sc; t.y = bb - mm * sc;
        } else { t.x = 0.f; t.y = -1.f; }
        th[i2] = t;
    }
}

// Pack s8 weights, exact mma B-fragment order.
// uint32 index r within layer: h=r&1, lane=(r>>1)&31, nf=(r>>6)&7, c2=r>>9,
// chunk=c2%KC, ct=c2/KC; tap=chunk/WINP, cw=chunk%WINP;
// co = ct*64+nf*8+lane/4, ci = cw*32 + (lane%4)*4 + h*16 + bytej.
__global__ void pack_wi8_kernel(const float* __restrict__ w1, const float* __restrict__ w2,
                                const float* __restrict__ w3, const float* __restrict__ w4,
                                const float* __restrict__ w5, uint32_t* __restrict__ dst)
{
    const int cum[6]  = {0, 331776, 940032, 2055168, 4082688, 7031808};
    const int kc[5]   = {108, 108, 198, 198, 360};
    const int winp[5] = {12, 12, 22, 22, 40};
    const int cin[5]  = {344, 352, 686, 679, 1246};
    const int cout[5] = {352, 686, 679, 1246, 973};
    int idx = blockIdx.x * blockDim.x + threadIdx.x;
    if (idx >= 7031808) return;
    int l = 0;
#pragma unroll
    for (int i = 1; i < 5; ++i) if (idx >= cum[i]) l = i;
    int r = idx - cum[l];
    int h = r & 1;
    int lane = (r >> 1) & 31;
    int nf = (r >> 6) & 7;
    int c2 = r >> 9;
    int chunk = c2 % kc[l];
    int ct = c2 / kc[l];
    int tap = chunk / winp[l];
    int cw = chunk - tap * winp[l];
    int co = ct * 64 + nf * 8 + (lane >> 2);
    int cib = cw * 32 + (lane & 3) * 4 + h * 16;
    const float* ws = (l == 0) ? w1 : (l == 1) ? w2 : (l == 2) ? w3 : (l == 3) ? w4 : w5;
    const int Ci = cin[l], Co = cout[l];
    uint32_t v = 0;
#pragma unroll
    for (int j = 0; j < 4; ++j) {
        int ci = cib + j;
        uint32_t byte = 0;
        if (co < Co && ci < Ci)
            byte = (ws[((size_t)co * Ci + ci) * 9 + tap] > 0.f) ? 0x01u : 0xFFu;
        v |= byte << (j * 8);
    }
    dst[idx] = v;
}

// ---------------------------------------------------------------------------
// Layer 0: bitwise XNOR conv (Cin=3, 1 word).
__global__ void __launch_bounds__(256)
bconv0_kernel(const uint32_t* __restrict__ in, uint8_t* __restrict__ out,
              const uint32_t* __restrict__ wpk, const int* __restrict__ pw,
              const float2* __restrict__ th)
{
    const int H = 32, W = 32, Cin = 3, WOUTP = 12;
    __shared__ uint32_t sw[288];
    __shared__ int spw[288];
    __shared__ uint32_t sx[100];
    const int tid = threadIdx.x;
    const int wi = blockIdx.y;
    const int x0 = (blockIdx.x & 3) * 8;
    const int y0 = (blockIdx.x >> 2) * 8;

    if (tid < 288) { sw[tid] = wpk[wi * 288 + tid]; spw[tid] = pw[wi * 288 + tid]; }
    { int i2 = tid + 256; if (i2 < 288) { sw[i2] = wpk[wi * 288 + i2]; spw[i2] = pw[wi * 288 + i2]; } }

    const int g  = tid >> 6;
    const int p  = tid & 63;
    const int py = p >> 3, px = p & 7;
    const int y  = y0 + py, x = x0 + px;
    const bool eT = (y == 0), eB = (y == H - 1), eL = (x == 0), eR = (x == W - 1);
    const bool edge = eT | eB | eL | eR;
    const int nvCin = (3 - (int)eT - (int)eB) * (3 - (int)eL - (int)eR) * Cin;

    float2 t8[8];
#pragma unroll
    for (int j = 0; j < 8; ++j) t8[j] = th[wi * 32 + g * 8 + j];

    for (int it = 0; it < IMGS_PER_BLK; ++it) {
        const int n = blockIdx.z * IMGS_PER_BLK + it;
        __syncthreads();
        const uint32_t* ibase = in + (size_t)n * 1024;
        for (int i = tid; i < 100; i += 256) {
            const int iy = y0 + i / 10 - 1;
            const int ix = x0 + i % 10 - 1;
            sx[i] = (iy >= 0 && iy < H && ix >= 0 && ix < W) ? ibase[iy * W + ix] : 0u;
        }
        __syncthreads();

        int D[8];
#pragma unroll
        for (int j = 0; j < 8; ++j) D[j] = 0;
        const uint32_t* xp = &sx[py * 10 + px];
        const uint32_t* wp = &sw[g * 8];
#pragma unroll
        for (int ky = 0; ky < 3; ++ky)
#pragma unroll
            for (int kx = 0; kx < 3; ++kx) {
                const uint32_t xv = xp[ky * 10 + kx];
                const uint32_t* wb = wp + (ky * 3 + kx) * 32;
#pragma unroll
                for (int j = 0; j < 8; ++j) D[j] += __popc(xv ^ wb[j]);
            }
        unsigned bytev = 0u;
#pragma unroll
        for (int j = 0; j < 8; ++j) {
            int corr = 0;
            if (edge) {
#pragma unroll
                for (int ky = 0; ky < 3; ++ky)
#pragma unroll
                    for (int kx = 0; kx < 3; ++kx) {
                        const bool inv = (eT && ky == 0) || (eB && ky == 2)
                                      || (eL && kx == 0) || (eR && kx == 2);
                        if (inv) corr += spw[(ky * 3 + kx) * 32 + g * 8 + j];
                    }
            }
            const int idot = nvCin - 2 * D[j] + 2 * corr;
            if (fmaf((float)idot, t8[j].x, t8[j].y) > 0.0f) bytev |= 1u << j;
        }
        out[(((size_t)n * 1024 + (size_t)y * W + x) * WOUTP + wi) * 4 + g] = (uint8_t)bytev;
    }
}

// ---------------------------------------------------------------------------
// mma.sync s8 implicit-GEMM binary conv (layers 1-5).
// CTA: 256 pixels x 64 couts. Warp: 32 pixels (2 x m16) x 64 couts (8 x n8).
// A decoded on the fly: nibble -> 4 bytes of {+1,-1} via smem LUT; halo -> 0.
template <int H, int WINP, int WOUT>
__global__ void __launch_bounds__(256, 2)
imma_conv(const uint32_t* __restrict__ in, uint32_t* __restrict__ out,
          const uint2* __restrict__ wB, const float2* __restrict__ thg)
{
    constexpr int W = H;
    constexpr int KC = 9 * WINP;
    __shared__ uint32_t lut[32];
    __shared__ float2 sth[64];
    const int tid = threadIdx.x;
    if (tid < 32) {
        uint32_t s2 = ((uint32_t)tid * 0x408102u) & 0x02020202u;
        lut[tid] = (tid < 16) ? __vsub4(s2, 0x01010101u) : 0u;
    }
    for (int i = tid; i < 64; i += 256) sth[i] = thg[blockIdx.y * 64 + i];
    __syncthreads();

    const int warp = tid >> 5;
    const int lane = tid & 31;
    const int q = lane & 3, r = lane >> 2;
    const int ct = blockIdx.y;
    const int s0 = q * 4;

    const int pixBase = blockIdx.x * 256 + warp * 32;
    int pn[4], py[4], pxx[4];
#pragma unroll
    for (int j = 0; j < 4; ++j) {
        int p = pixBase + r + j * 8;
        int n = p / (H * W);
        int rem = p - n * (H * W);
        pn[j] = n; py[j] = rem / W; pxx[j] = rem - (rem / W) * W;
    }

    int acc[2][8][4];
#pragma unroll
    for (int f = 0; f < 2; ++f)
#pragma unroll
        for (int nf = 0; nf < 8; ++nf)
#pragma unroll
            for (int k = 0; k < 4; ++k) acc[f][nf][k] = 0;

    const uint2* bp = wB + (size_t)ct * KC * 256 + lane;

#pragma unroll 1
    for (int tap = 0; tap < 9; ++tap) {
        const int dy = tap / 3 - 1, dx = tap % 3 - 1;
        const uint32_t* ap[4];
        uint32_t ivm[4];
#pragma unroll
        for (int j = 0; j < 4; ++j) {
            int yy = py[j] + dy, xx = pxx[j] + dx;
            bool v = ((unsigned)yy < (unsigned)H) && ((unsigned)xx < (unsigned)W);
            int yc = v ? yy : 0, xc = v ? xx : 0;
            ap[j] = in + ((size_t)(pn[j] * H + yc) * W + xc) * WINP;
            ivm[j] = v ? 0u : 16u;
        }
        const uint2* bc = bp + (size_t)tap * WINP * 256;
#pragma unroll 1
        for (int cw = 0; cw < WINP; ++cw) {
            uint32_t aF0[4], aF1[4];
#pragma unroll
            for (int j = 0; j < 4; ++j) {
                const uint32_t w = ap[j][cw];
                const uint32_t lo = lut[((w >> s0) & 0xFu) | ivm[j]];
                const uint32_t hi = lut[((w >> (s0 + 16)) & 0xFu) | ivm[j]];
                if (j == 0)      { aF0[0] = lo; aF0[2] = hi; }
                else if (j == 1) { aF0[1] = lo; aF0[3] = hi; }
                else if (j == 2) { aF1[0] = lo; aF1[2] = hi; }
                else             { aF1[1] = lo; aF1[3] = hi; }
            }
            const uint2* bcc = bc + (size_t)cw * 256;
#pragma unroll
            for (int nf = 0; nf < 8; ++nf) {
                const uint2 b = __ldg(bcc + nf * 32);
                imma_16832(acc[0][nf], aF0, b);
                imma_16832(acc[1][nf], aF1, b);
            }
        }
    }

    // Epilogue: threshold, assemble packed words via shfl-OR over the 4 q-lanes.
#pragma unroll
    for (int j = 0; j < 4; ++j) {
        const int f = j >> 1, hp = (j & 1) * 2;
        uint32_t w0 = 0, w1 = 0;
#pragma unroll
        for (int nf = 0; nf < 8; ++nf) {
            const float2 t0 = sth[nf * 8 + q * 2];
            const float2 t1 = sth[nf * 8 + q * 2 + 1];
            const int v0 = acc[f][nf][hp];
            const int v1 = acc[f][nf][hp + 1];
            uint32_t bits = 0;
            if (fmaf((float)v0, t0.x, t0.y) > 0.f) bits |= 1u;
            if (fmaf((float)v1, t1.x, t1.y) > 0.f) bits |= 2u;
            if (nf < 4) w0 |= bits << (nf * 8 + q * 2);
            else        w1 |= bits << ((nf - 4) * 8 + q * 2);
        }
        w0 |= __shfl_xor_sync(0xFFFFFFFFu, w0, 1);
        w0 |= __shfl_xor_sync(0xFFFFFFFFu, w0, 2);
        w1 |= __shfl_xor_sync(0xFFFFFFFFu, w1, 1);
        w1 |= __shfl_xor_sync(0xFFFFFFFFu, w1, 2);
        if (q == 0) {
            const int p = pixBase + r + j * 8;
            out[(size_t)p * WOUT + ct * 2]     = w0;
            out[(size_t)p * WOUT + ct * 2 + 1] = w1;
        }
    }
}

// ---------------------------------------------------------------------------
__global__ void pool_kernel(const uint32_t* __restrict__ in, uint32_t* __restrict__ out,
                            int Ho, int Wo, int WORDS, int total)
{
    int idx = blockIdx.x * blockDim.x + threadIdx.x;
    if (idx >= total) return;
    int w = idx % WORDS; int r = idx / WORDS;
    int xo = r % Wo; r /= Wo;
    int yo = r % Ho; int n = r / Ho;
    const int Wi = Wo * 2;
    size_t base = (((size_t)n * (Ho * 2) + yo * 2) * Wi + xo * 2) * WORDS + w;
    size_t rs = (size_t)Wi * WORDS;
    out[idx] = in[base] | in[base + WORDS] | in[base + rs] | in[base + rs + WORDS];
}

__global__ void fc_kernel(const uint32_t* __restrict__ xb, const uint32_t* __restrict__ wb,
                          const float* __restrict__ fcb, float* __restrict__ out)
{
    int t = blockIdx.x * blockDim.x + threadIdx.x;
    if (t >= NIMG * 10) return;
    int n = t / 10, o = t - n * 10;
    const uint4* xa = (const uint4*)(xb + (size_t)n * 512);
    const uint4* wa = (const uint4*)(wb + (size_t)o * 512);
    int D = 0;
#pragma unroll 8
    for (int i = 0; i < 128; ++i) {
        uint4 a = xa[i], b = wa[i];
        D += __popc(a.x ^ b.x) + __popc(a.y ^ b.y) + __popc(a.z ^ b.z) + __popc(a.w ^ b.w);
    }
    out[t] = (float)(15568 - 2 * D) + fcb[o];
}

// ---------------------------------------------------------------------------
extern "C" void kernel_launch(void* const* d_in, const int* in_sizes, int n_in,
                              void* d_out, int out_size)
{
    const long long szw[6] = {344LL*3*9, 352LL*344*9, 686LL*352*9,
                              679LL*686*9, 1246LL*679*9, 973LL*1246*9};
    const long long szp[6] = {4LL*344, 4LL*352, 4LL*686, 4LL*679, 4LL*1246, 4LL*973};
    auto find = [&](long long s) -> const void* {
        for (int i = 0; i < n_in; ++i)
            if ((long long)in_sizes[i] == s) return d_in[i];
        return (const void*)0;
    };
    const float* x   = (const float*)find(256LL * 3 * 32 * 32);
    const float* fcw = (const float*)find(10LL * 15568);
    const float* fcb = (const float*)find(10);
    const float* w[6]; const float* p[6];
    for (int i = 0; i < 6; ++i) {
        w[i] = (const float*)find(szw[i]);
        p[i] = (const float*)find(szp[i]);
    }
    if (!x || !fcw || !fcb) return;

    void *pA, *pB, *pW0, *pPW, *pT, *pF, *pWI;
    cudaGetSymbolAddress(&pA, g_bufA);
    cudaGetSymbolAddress(&pB, g_bufB);
    cudaGetSymbolAddress(&pW0, g_wpk0);
    cudaGetSymbolAddress(&pPW, g_pw0);
    cudaGetSymbolAddress(&pT, g_th);
    cudaGetSymbolAddress(&pF, g_fcpk);
    cudaGetSymbolAddress(&pWI, g_wi8);
    uint32_t* bufA = (uint32_t*)pA;
    uint32_t* bufB = (uint32_t*)pB;
    uint32_t* wpk0 = (uint32_t*)pW0;
    int*      pw0  = (int*)pPW;
    float2*   th   = (float2*)pT;
    uint32_t* fcpk = (uint32_t*)pF;
    uint2*    wi8  = (uint2*)pWI;

    // --- packs ---
    {   int tot = NIMG * 1024 + 3456 * 32;
        pack_xw_kernel<<<(tot + 255) / 256, 256>>>(x, w[0], bufA, wpk0); }
    {   int tot = 163840 + 3456 + 4480;
        pack_misc_kernel<<<(tot + 255) / 256, 256>>>(wpk0, fcw, p[0], p[1], p[2], p[3],
                                                     p[4], p[5], pw0, th, fcpk); }
    pack_wi8_kernel<<<(7031808 + 255) / 256, 256>>>(w[1], w[2], w[3], w[4], w[5],
                                                    (uint32_t*)wi8);

    // --- layer 0 (bitwise) ---
    bconv0_kernel<<<dim3(16, 12, NIMG / IMGS_PER_BLK), 256>>>(
        bufA, (uint8_t*)bufB, wpk0, pw0, th);

    // wi8 per-layer offsets (uint2): {0, 165888, 470016, 1027584, 2041344}
    // conv1: bufB [32,32,12] -> bufA [32,32,12]
    imma_conv<32, 12, 12><<<dim3(1024, 6), 256>>>(bufB, bufA, wi8 + 0, th + 384);
    // pool1 -> bufB [16,16,12]
    {   int tot = NIMG * 16 * 16 * 12;
        pool_kernel<<<(tot + 255) / 256, 256>>>(bufA, bufB, 16, 16, 12, tot); }
    // conv2: bufB -> bufA [16,16,22]
    imma_conv<16, 12, 22><<<dim3(256, 11), 256>>>(bufB, bufA, wi8 + 165888, th + 768);
    // conv3: bufA -> bufB [16,16,22]
    imma_conv<16, 22, 22><<<dim3(256, 11), 256>>>(bufA, bufB, wi8 + 470016, th + 1472);
    // pool2 -> bufA [8,8,22]
    {   int tot = NIMG * 8 * 8 * 22;
        pool_kernel<<<(tot + 255) / 256, 256>>>(bufB, bufA, 8, 8, 22, tot); }
    // conv4: bufA -> bufB [8,8,40]
    imma_conv<8, 22, 40><<<dim3(64, 20), 256>>>(bufA, bufB, wi8 + 1027584, th + 2176);
    // conv5: bufB -> bufA [8,8,32]
    imma_conv<8, 40, 32><<<dim3(64, 16), 256>>>(bufB, bufA, wi8 + 2041344, th + 3456);
    // pool3 -> bufB [4,4,32]
    {   int tot = NIMG * 4 * 4 * 32;
        pool_kernel<<<(tot + 255) / 256, 256>>>(bufA, bufB, 4, 4, 32, tot); }

    // --- FC ---
    fc_kernel<<<10, 256>>>(bufB, fcpk, fcb, (float*)d_out);
}

// round 8
// speedup vs baseline: 2.3722x; 2.3722x over previous
#include <cuda_runtime.h>
#include <cstdint>

#define NIMG 256
#define IMGS_PER_BLK 8

// Layers: cin {3,344,352,686,679,1246} cout {344,352,686,679,1246,973}
// conv H=W {32,32,16,16,8,8}, pool after 1,3,5
// WINP {1,12,12,24,24,40}, WOUTP {12,12,24,24,40,32}
// Packed weight words/layer: cum {0,3456,44928,127872,293760,570240}, tot 938880

__device__ uint32_t g_bufA[(size_t)NIMG * 32 * 32 * 12];
__device__ uint32_t g_bufB[(size_t)NIMG * 32 * 32 * 12];
__device__ uint32_t g_wpk[938880];
__device__ int      g_wpw[41472];        // per (layer, wi, tap, cl): popc of weight row
__device__ float2   g_th[4608];          // per-channel (scale, beta - mean*scale)
__device__ uint32_t g_fcpk[10 * 16 * 32];

// Force IMAD (fma pipe) for accumulation; k is a runtime-opaque 1 or 2.
__device__ __forceinline__ void madacc(int& d, int p, int k) {
    asm("mad.lo.s32 %0, %1, %2, %0;" : "+r"(d) : "r"(p), "r"(k));
}

// ---------------------------------------------------------------------------
// Merged pack: x activations (first 262144 threads) + all conv weights (warp ballot).
__global__ void pack_xw_kernel(const float* __restrict__ x,
                               const float* __restrict__ w0, const float* __restrict__ w1,
                               const float* __restrict__ w2, const float* __restrict__ w3,
                               const float* __restrict__ w4, const float* __restrict__ w5,
                               uint32_t* __restrict__ dstx, uint32_t* __restrict__ dstw)
{
    int idx = blockIdx.x * blockDim.x + threadIdx.x;
    if (idx < NIMG * 1024) {
        int n = idx >> 10, pix = idx & 1023;
        const float* xb = x + (size_t)n * 3 * 1024 + pix;
        uint32_t w = 0;
        if (xb[0]    > 0.f) w |= 1u;
        if (xb[1024] > 0.f) w |= 2u;
        if (xb[2048] > 0.f) w |= 4u;
        dstx[idx] = w;
        return;
    }
    const int cum[7]  = {0, 3456, 44928, 127872, 293760, 570240, 938880};
    const int cin[6]  = {3, 344, 352, 686, 679, 1246};
    const int cout[6] = {344, 352, 686, 679, 1246, 973};
    const int winp[6] = {1, 12, 12, 24, 24, 40};

    int warp = (idx >> 5) - 8192;
    int lane = idx & 31;
    if (warp >= 938880) return;

    int l = 0;
#pragma unroll
    for (int i = 1; i < 6; ++i) if (warp >= cum[i]) l = i;

    const float* wsrc = (l == 0) ? w0 : (l == 1) ? w1 : (l == 2) ? w2
                       : (l == 3) ? w3 : (l == 4) ? w4 : w5;
    const int Ci = cin[l], Co = cout[l], WINP = winp[l];

    int widx = warp - cum[l];
    int q   = widx % WINP;  widx /= WINP;
    int cl  = widx & 31;    widx >>= 5;
    int tap = widx % 9;
    int wi  = widx / 9;
    int co  = wi * 32 + cl;
    int ci  = q * 32 + lane;

    float v = 0.f;
    if (co < Co && ci < Ci)
        v = wsrc[((size_t)co * Ci + ci) * 9 + tap];
    uint32_t bits = __ballot_sync(0xFFFFFFFFu, v > 0.f);
    if (lane == 0) dstw[warp] = bits;
}

// ---------------------------------------------------------------------------
// Merged pack: FC weights ballot + per-tap weight popcounts + BN thresholds.
__global__ void pack_misc_kernel(const uint32_t* __restrict__ wpk,
                                 const float* __restrict__ fcw,
                                 const float* __restrict__ p0, const float* __restrict__ p1,
                                 const float* __restrict__ p2, const float* __restrict__ p3,
                                 const float* __restrict__ p4, const float* __restrict__ p5,
                                 int* __restrict__ pw, float2* __restrict__ th,
                                 uint32_t* __restrict__ fcpk)
{
    int idx = blockIdx.x * blockDim.x + threadIdx.x;
    if (idx < 163840) {
        int warp = idx >> 5;
        int lane = idx & 31;
        int wi = warp & 31; int r = warp >> 5;
        int s = r & 15; int o = r >> 4;
        int c = wi * 32 + lane;
        float v = (c < 973) ? fcw[(size_t)o * 15568 + c * 16 + s] : 0.f;
        uint32_t bits = __ballot_sync(0xFFFFFFFFu, v > 0.f);
        if (lane == 0) fcpk[warp] = bits;
    } else if (idx < 163840 + 41472) {
        int i1 = idx - 163840;
        const int cum9[7]  = {0, 3456, 6912, 13824, 20736, 32256, 41472};
        const int woff[6]  = {0, 3456, 44928, 127872, 293760, 570240};
        const int winp[6]  = {1, 12, 12, 24, 24, 40};
        int l = 0;
#pragma unroll
        for (int i = 1; i < 6; ++i) if (i1 >= cum9[i]) l = i;
        int t = i1 - cum9[l];
        int cl  = t & 31;  t >>= 5;
        int tap = t % 9;
        int wi  = t / 9;
        const int WINP = winp[l];
        const uint32_t* src = wpk + woff[l] + (((size_t)wi * 9 + tap) * 32 + cl) * WINP;
        int s = 0;
        for (int q = 0; q < WINP; ++q) s += __popc(src[q]);
        pw[i1] = s;
    } else if (idx < 163840 + 41472 + 4608) {
        int i2 = idx - 163840 - 41472;
        const int cum[7]  = {0, 384, 768, 1536, 2304, 3584, 4608};
        const int cout[6] = {344, 352, 686, 679, 1246, 973};
        int l = 0;
#pragma unroll
        for (int i = 1; i < 6; ++i) if (i2 >= cum[i]) l = i;
        const float* p = (l == 0) ? p0 : (l == 1) ? p1 : (l == 2) ? p2
                        : (l == 3) ? p3 : (l == 4) ? p4 : p5;
        int c = i2 - cum[l];
        int Co = cout[l];
        float2 t;
        if (c < Co) {
            float gg = p[c], bb = p[Co + c], mm = p[2 * Co + c], vv = p[3 * Co + c];
            float sc = gg * rsqrtf(vv + 1e-5f);
            t.x = sc; t.y = bb - mm * sc;
        } else {
            t.x = 0.f; t.y = -1.f;
        }
        th[i2] = t;
    }
}

// ---------------------------------------------------------------------------
// Binary conv 3x3 pad 1, branch-free all-9-taps + edge correction.
// CSA compression (2 POPC per 3 words); accumulation forced onto the fma pipe
// via mad.lo.s32 with runtime-opaque multipliers (one=1, two=2); single
// accumulator D = D1 + 2*D2. Thresholds loaded from global at epilogue.
template <int WINP>
__global__ void __launch_bounds__(256, 4)
bconv_kernel(const uint32_t* __restrict__ in, uint8_t* __restrict__ out,
             const uint32_t* __restrict__ wpk, const int* __restrict__ pw,
             const float2* __restrict__ th,
             int H, int W, int Cin, int WOUTP, int tilesX, int one, int two)
{
    extern __shared__ uint32_t sm[];
    uint32_t* sw  = sm;                           // 9*32*WINP
    int*      spw = (int*)(sm + 9 * 32 * WINP);   // 9*32
    uint32_t* sx  = sm + 9 * 32 * WINP + 288;     // 10*10*WINP
    const int tid = threadIdx.x;
    const int wi = blockIdx.y;
    const int x0 = (blockIdx.x % tilesX) * 8;
    const int y0 = (blockIdx.x / tilesX) * 8;

    const uint32_t* wsrc = wpk + (size_t)wi * (9 * 32 * WINP);
    for (int i = tid; i < 9 * 32 * WINP; i += 256) sw[i] = wsrc[i];
    if (tid < 288) spw[tid] = pw[(size_t)wi * 288 + tid];
    { int i2 = tid + 256; if (i2 < 288) spw[i2] = pw[(size_t)wi * 288 + i2]; }

    const int g  = tid >> 6;
    const int p  = tid & 63;
    const int py = p >> 3;
    const int px = p & 7;
    const int y  = y0 + py, x = x0 + px;
    const bool eT = (y == 0), eB = (y == H - 1), eL = (x == 0), eR = (x == W - 1);
    const bool edge = eT | eB | eL | eR;
    const int nv = (3 - (int)eT - (int)eB) * (3 - (int)eL - (int)eR);
    const int nvCin = nv * Cin;

    for (int it = 0; it < IMGS_PER_BLK; ++it) {
        const int n = blockIdx.z * IMGS_PER_BLK + it;
        __syncthreads();
        const uint32_t* ibase = in + (size_t)n * H * W * WINP;
        for (int i = tid; i < 100 * WINP; i += 256) {
            const int w  = i % WINP;
            const int pp = i / WINP;
            const int iy = y0 + pp / 10 - 1;
            const int ix = x0 + pp % 10 - 1;
            uint32_t v = 0u;
            if (iy >= 0 && iy < H && ix >= 0 && ix < W)
                v = ibase[((size_t)iy * W + ix) * WINP + w];
            sx[i] = v;
        }
        __syncthreads();

        int D[8];
#pragma unroll
        for (int j = 0; j < 8; ++j) D[j] = 0;

        const uint32_t* xp = &sx[(py * 10 + px) * WINP];
        const uint32_t* wp = &sw[(g * 8) * WINP];
#pragma unroll 1
        for (int ky = 0; ky < 3; ++ky) {
#pragma unroll 1
            for (int kx = 0; kx < 3; ++kx) {
                if (WINP == 1) {
                    const uint32_t xv = xp[0];
#pragma unroll
                    for (int j = 0; j < 8; ++j)
                        madacc(D[j], __popc(xv ^ wp[j]), one);
                } else {
#pragma unroll
                    for (int t3 = 0; t3 < WINP / 12; ++t3) {
                        const uint4 x0v = *(const uint4*)(xp + t3 * 12);
                        const uint4 x1v = *(const uint4*)(xp + t3 * 12 + 4);
                        const uint4 x2v = *(const uint4*)(xp + t3 * 12 + 8);
#pragma unroll
                        for (int j = 0; j < 8; ++j) {
                            const uint32_t* wj = wp + j * WINP + t3 * 12;
                            const uint4 w0v = *(const uint4*)(wj);
                            const uint4 w1v = *(const uint4*)(wj + 4);
                            const uint4 w2v = *(const uint4*)(wj + 8);
                            uint32_t a, b, c;
                            uint32_t s0, s1, s2, s3, m0, m1, m2, m3;
                            a = x0v.x ^ w0v.x; b = x1v.x ^ w1v.x; c = x2v.x ^ w2v.x;
                            s0 = a ^ b ^ c; m0 = (a & b) | (c & (a | b));
                            a = x0v.y ^ w0v.y; b = x1v.y ^ w1v.y; c = x2v.y ^ w2v.y;
                            s1 = a ^ b ^ c; m1 = (a & b) | (c & (a | b));
                            a = x0v.z ^ w0v.z; b = x1v.z ^ w1v.z; c = x2v.z ^ w2v.z;
                            s2 = a ^ b ^ c; m2 = (a & b) | (c & (a | b));
                            a = x0v.w ^ w0v.w; b = x1v.w ^ w1v.w; c = x2v.w ^ w2v.w;
                            s3 = a ^ b ^ c; m3 = (a & b) | (c & (a | b));
                            int ps = __popc(s0) + __popc(s1) + __popc(s2);
                            madacc(D[j], ps, one);
                            madacc(D[j], __popc(s3), one);
                            int pm = __popc(m0) + __popc(m1) + __popc(m2);
                            madacc(D[j], pm, two);
                            madacc(D[j], __popc(m3), two);
                        }
                    }
                    if (WINP - (WINP / 12) * 12 == 4) {   // WINP=40 leftover uint4
                        const uint4 xv = *(const uint4*)(xp + (WINP / 12) * 12);
#pragma unroll
                        for (int j = 0; j < 8; ++j) {
                            const uint4 wv = *(const uint4*)(wp + j * WINP + (WINP / 12) * 12);
                            int pl = __popc(xv.x ^ wv.x) + __popc(xv.y ^ wv.y)
                                   + __popc(xv.z ^ wv.z);
                            madacc(D[j], pl, one);
                            madacc(D[j], __popc(xv.w ^ wv.w), one);
                        }
                    }
                }
                xp += WINP;
                wp += 32 * WINP;
            }
            xp += 7 * WINP;
        }

        unsigned bytev = 0u;
#pragma unroll
        for (int j = 0; j < 8; ++j) {
            int corr = 0;
            if (edge) {
#pragma unroll
                for (int ky = 0; ky < 3; ++ky)
#pragma unroll
                    for (int kx = 0; kx < 3; ++kx) {
                        const bool inv = (eT && ky == 0) || (eB && ky == 2)
                                      || (eL && kx == 0) || (eR && kx == 2);
                        if (inv) corr += spw[(ky * 3 + kx) * 32 + g * 8 + j];
                    }
            }
            const int idot = nvCin - 2 * D[j] + 2 * corr;
            const float2 t = __ldg(&th[wi * 32 + g * 8 + j]);
            if (fmaf((float)idot, t.x, t.y) > 0.0f) bytev |= 1u << j;
        }
        out[(((size_t)n * H * W + (size_t)y * W + x) * WOUTP + wi) * 4 + g]
            = (uint8_t)bytev;
    }
}

// Maxpool 2x2 on packed bits == bitwise OR (BN scale > 0, monotone)
__global__ void pool_kernel(const uint32_t* __restrict__ in, uint32_t* __restrict__ out,
                            int Ho, int Wo, int WORDS, int total)
{
    int idx = blockIdx.x * blockDim.x + threadIdx.x;
    if (idx >= total) return;
    int w = idx % WORDS; int r = idx / WORDS;
    int xo = r % Wo; r /= Wo;
    int yo = r % Ho; int n = r / Ho;
    const int Wi = Wo * 2;
    size_t base = (((size_t)n * (Ho * 2) + yo * 2) * Wi + xo * 2) * WORDS + w;
    size_t rs = (size_t)Wi * WORDS;
    out[idx] = in[base] | in[base + WORDS] | in[base + rs] | in[base + rs + WORDS];
}

// Binary FC: out[n][o] = 15568 - 2*popc(x ^ w) + fcb[o]
__global__ void fc_kernel(const uint32_t* __restrict__ xb, const uint32_t* __restrict__ wb,
                          const float* __restrict__ fcb, float* __restrict__ out)
{
    int t = blockIdx.x * blockDim.x + threadIdx.x;
    if (t >= NIMG * 10) return;
    int n = t / 10, o = t - n * 10;
    const uint4* xa = (const uint4*)(xb + (size_t)n * 512);
    const uint4* wa = (const uint4*)(wb + (size_t)o * 512);
    int D = 0;
#pragma unroll 8
    for (int i = 0; i < 128; ++i) {
        uint4 a = xa[i], b = wa[i];
        D += __popc(a.x ^ b.x) + __popc(a.y ^ b.y) + __popc(a.z ^ b.z) + __popc(a.w ^ b.w);
    }
    out[t] = (float)(15568 - 2 * D) + fcb[o];
}

// ---------------------------------------------------------------------------
extern "C" void kernel_launch(void* const* d_in, const int* in_sizes, int n_in,
                              void* d_out, int out_size)
{
    static const int s_cin[6]   = {3, 344, 352, 686, 679, 1246};
    static const int s_H[6]     = {32, 32, 16, 16, 8, 8};
    static const int s_winp[6]  = {1, 12, 12, 24, 24, 40};
    static const int s_woutp[6] = {12, 12, 24, 24, 40, 32};
    static const size_t s_woff[6] = {0, 3456, 44928, 127872, 293760, 570240};
    static const size_t s_toff[6] = {0, 384, 768, 1536, 2304, 3584};

    const long long szw[6] = {344LL*3*9, 352LL*344*9, 686LL*352*9,
                              679LL*686*9, 1246LL*679*9, 973LL*1246*9};
    const long long szp[6] = {4LL*344, 4LL*352, 4LL*686, 4LL*679, 4LL*1246, 4LL*973};
    auto find = [&](long long s) -> const void* {
        for (int i = 0; i < n_in; ++i)
            if ((long long)in_sizes[i] == s) return d_in[i];
        return (const void*)0;
    };
    const float* x   = (const float*)find(256LL * 3 * 32 * 32);
    const float* fcw = (const float*)find(10LL * 15568);
    const float* fcb = (const float*)find(10);
    const float* w[6]; const float* p[6];
    for (int i = 0; i < 6; ++i) {
        w[i] = (const float*)find(szw[i]);
        p[i] = (const float*)find(szp[i]);
    }
    if (!x || !fcw || !fcb) return;

    void *pA, *pB, *pW, *pPW, *pT, *pF;
    cudaGetSymbolAddress(&pA, g_bufA);
    cudaGetSymbolAddress(&pB, g_bufB);
    cudaGetSymbolAddress(&pW, g_wpk);
    cudaGetSymbolAddress(&pPW, g_wpw);
    cudaGetSymbolAddress(&pT, g_th);
    cudaGetSymbolAddress(&pF, g_fcpk);
    uint32_t* bufA = (uint32_t*)pA;
    uint32_t* bufB = (uint32_t*)pB;
    uint32_t* wpk  = (uint32_t*)pW;
    int*      wpw  = (int*)pPW;
    float2*   th   = (float2*)pT;
    uint32_t* fcpk = (uint32_t*)pF;

    auto smemFor = [](int winp) { return (size_t)(9 * 32 * winp + 288 + 100 * winp) * 4; };
    cudaFuncSetAttribute(bconv_kernel<40>, cudaFuncAttributeMaxDynamicSharedMemorySize, (int)smemFor(40));
    cudaFuncSetAttribute(bconv_kernel<24>, cudaFuncAttributeMaxDynamicSharedMemorySize, (int)smemFor(24));

    // --- pack phase: 2 launches ---
    {
        int tot = NIMG * 1024 + 938880 * 32;
        pack_xw_kernel<<<(tot + 255) / 256, 256>>>(x, w[0], w[1], w[2], w[3], w[4], w[5],
                                                   bufA, wpk);
    }
    {
        int tot = 163840 + 41472 + 4608;
        pack_misc_kernel<<<(tot + 255) / 256, 256>>>(wpk, fcw, p[0], p[1], p[2], p[3], p[4], p[5],
                                                     wpw, th, fcpk);
    }

    // --- conv stack ---
    auto conv = [&](int l, const uint32_t* src, uint32_t* dst) {
        int H = s_H[l], W = H;
        int WINP = s_winp[l], WOUTP = s_woutp[l], Cin = s_cin[l];
        int tilesX = (W + 7) / 8;
        dim3 grid((unsigned)(((H + 7) / 8) * tilesX), (unsigned)WOUTP,
                  (unsigned)(NIMG / IMGS_PER_BLK));
        size_t smem = smemFor(WINP);
        uint8_t* ob = (uint8_t*)dst;
        const uint32_t* wb = wpk + s_woff[l];
        const int* pwb = wpw + s_toff[l] * 9;
        const float2* tb = th + s_toff[l];
        switch (WINP) {
            case 1:  bconv_kernel<1><<<grid, 256, smem>>>(src, ob, wb, pwb, tb, H, W, Cin, WOUTP, tilesX, 1, 2); break;
            case 12: bconv_kernel<12><<<grid, 256, smem>>>(src, ob, wb, pwb, tb, H, W, Cin, WOUTP, tilesX, 1, 2); break;
            case 24: bconv_kernel<24><<<grid, 256, smem>>>(src, ob, wb, pwb, tb, H, W, Cin, WOUTP, tilesX, 1, 2); break;
            case 40: bconv_kernel<40><<<grid, 256, smem>>>(src, ob, wb, pwb, tb, H, W, Cin, WOUTP, tilesX, 1, 2); break;
        }
    };

    conv(0, bufA, bufB);                                    // B: [32,32,12]
    conv(1, bufB, bufA);                                    // A: conv-space [32,32,12]
    {   int tot = NIMG * 16 * 16 * 12;
        pool_kernel<<<(tot + 255) / 256, 256>>>(bufA, bufB, 16, 16, 12, tot); }  // B: [16,16,12]
    conv(2, bufB, bufA);                                    // A: [16,16,24]
    conv(3, bufA, bufB);                                    // B: conv-space [16,16,24]
    {   int tot = NIMG * 8 * 8 * 24;
        pool_kernel<<<(tot + 255) / 256, 256>>>(bufB, bufA, 8, 8, 24, tot); }    // A: [8,8,24]
    conv(4, bufA, bufB);                                    // B: [8,8,40]
    conv(5, bufB, bufA);                                    // A: conv-space [8,8,32]
    {   int tot = NIMG * 4 * 4 * 32;
        pool_kernel<<<(tot + 255) / 256, 256>>>(bufA, bufB, 4, 4, 32, tot); }    // B: [4,4,32]

    // --- FC ---
    fc_kernel<<<10, 256>>>(bufB, fcpk, fcb, (float*)d_out);
}